// round 5
// baseline (speedup 1.0000x reference)
#include <cuda_runtime.h>
#include <float.h>

#define NB     2
#define NN     8192
#define KNN    20
#define COUT   64
#define NCLASS 40
#define BN_EPS 1e-5f
#define EPT    8

// Scratch (no allocations allowed)
__device__ alignas(16) float  g_A[NB * NN];
__device__ alignas(16) float4 g_pack[NB * NN];   // {x, dmin, dmax, 0}

// ---------------------------------------------------------------------------
// Compare-exchange helpers — ALL register indices compile-time constant.
// Global bitonic rule: at stage k, element i merges ascending iff (i&k)==0.
// ---------------------------------------------------------------------------
__device__ __forceinline__ void ce(float& a, float& b, bool up) {
    float mn = fminf(a, b), mx = fmaxf(a, b);
    a = up ? mn : mx;
    b = up ? mx : mn;
}

__device__ __forceinline__ void reg_merge(float v[EPT], bool d) {
    ce(v[0], v[4], d); ce(v[1], v[5], d); ce(v[2], v[6], d); ce(v[3], v[7], d);
    ce(v[0], v[2], d); ce(v[1], v[3], d); ce(v[4], v[6], d); ce(v[5], v[7], d);
    ce(v[0], v[1], d); ce(v[2], v[3], d); ce(v[4], v[5], d); ce(v[6], v[7], d);
}

__device__ __forceinline__ void sort8(float v[EPT], bool d8) {
    ce(v[0], v[1], true);  ce(v[2], v[3], false);
    ce(v[4], v[5], true);  ce(v[6], v[7], false);
    ce(v[0], v[2], true);  ce(v[1], v[3], true);
    ce(v[4], v[6], false); ce(v[5], v[7], false);
    ce(v[0], v[1], true);  ce(v[2], v[3], true);
    ce(v[4], v[5], false); ce(v[6], v[7], false);
    reg_merge(v, d8);
}

__device__ __forceinline__ void warp_merge(float v[EPT], bool d, int xm_start, int t) {
    for (int xm = xm_start; xm >= 1; xm >>= 1) {
        bool lowup = (((t & xm) == 0) == d);
        #pragma unroll
        for (int m = 0; m < EPT; m++) {
            float pv = __shfl_xor_sync(0xffffffffu, v[m], xm);
            v[m] = lowup ? fminf(v[m], pv) : fmaxf(v[m], pv);
        }
    }
    reg_merge(v, d);
}

// smem substages j = jstart..256, then intra-warp tail (j<=128).
template<int T>
__device__ __forceinline__ void block_merge(float v[EPT], float4* sA, int t,
                                            bool d, int jstart) {
    float4* sB = sA + T;
    for (int j = jstart; j >= 256; j >>= 1) {
        sA[t] = make_float4(v[0], v[1], v[2], v[3]);
        sB[t] = make_float4(v[4], v[5], v[6], v[7]);
        __syncthreads();
        const int  pt    = t ^ (j >> 3);
        const bool lowup = (((t & (j >> 3)) == 0) == d);
        float4 pa = sA[pt], pb = sB[pt];
        v[0] = lowup ? fminf(v[0], pa.x) : fmaxf(v[0], pa.x);
        v[1] = lowup ? fminf(v[1], pa.y) : fmaxf(v[1], pa.y);
        v[2] = lowup ? fminf(v[2], pa.z) : fmaxf(v[2], pa.z);
        v[3] = lowup ? fminf(v[3], pa.w) : fmaxf(v[3], pa.w);
        v[4] = lowup ? fminf(v[4], pb.x) : fmaxf(v[4], pb.x);
        v[5] = lowup ? fminf(v[5], pb.y) : fmaxf(v[5], pb.y);
        v[6] = lowup ? fminf(v[6], pb.z) : fmaxf(v[6], pb.z);
        v[7] = lowup ? fminf(v[7], pb.w) : fmaxf(v[7], pb.w);
        __syncthreads();
    }
    warp_merge(v, d, 16, t);
}

// ---------------------------------------------------------------------------
// DSMEM helpers
// ---------------------------------------------------------------------------
__device__ __forceinline__ float4 dsmem_read4(const float4* p, unsigned peer) {
    unsigned la = (unsigned)__cvta_generic_to_shared(p), ra;
    asm volatile("mapa.shared::cluster.u32 %0, %1, %2;" : "=r"(ra) : "r"(la), "r"(peer));
    float4 r;
    asm volatile("ld.shared::cluster.v4.f32 {%0,%1,%2,%3}, [%4];"
                 : "=f"(r.x), "=f"(r.y), "=f"(r.z), "=f"(r.w) : "r"(ra));
    return r;
}
__device__ __forceinline__ float dsmem_read1(const float* p, unsigned peer) {
    unsigned la = (unsigned)__cvta_generic_to_shared(p), ra;
    asm volatile("mapa.shared::cluster.u32 %0, %1, %2;" : "=r"(ra) : "r"(la), "r"(peer));
    float r;
    asm volatile("ld.shared::cluster.f32 %0, [%1];" : "=f"(r) : "r"(ra));
    return r;
}
#define CLUSTER_SYNC() do { \
    asm volatile("barrier.cluster.arrive.aligned;" ::: "memory"); \
    asm volatile("barrier.cluster.wait.aligned;"   ::: "memory"); \
} while (0)

// ---------------------------------------------------------------------------
// K1: sort each 2048-chunk (k = 2..2048). grid (4, NB) x 256 threads.
// Also zeroes d_out (poisoned by harness) for the atomic FC accumulation.
// ---------------------------------------------------------------------------
__global__ void __launch_bounds__(256, 1) k_sort2048(const float* __restrict__ x,
                                                     float* __restrict__ out) {
    __shared__ float4 s[512];                    // 2048 floats
    const int t = threadIdx.x;
    const int b = blockIdx.y, cx = blockIdx.x;
    if (b == 0 && cx == 0 && t < NB * NCLASS) out[t] = 0.f;

    const float4* src = (const float4*)(x + b * NN + cx * 2048);
    float v[EPT];
    { float4 a = src[t * 2], c = src[t * 2 + 1];
      v[0]=a.x; v[1]=a.y; v[2]=a.z; v[3]=a.w;
      v[4]=c.x; v[5]=c.y; v[6]=c.z; v[7]=c.w; }

    sort8(v, (t & 1) == 0);                              // k = 2,4,8
    for (int k = 16; k <= 256; k <<= 1)                  // k = 16..256
        warp_merge(v, (t & (k >> 3)) == 0, k >> 4, t);
    block_merge<256>(v, s, t, (t & 64)  == 0, 256);      // k = 512
    block_merge<256>(v, s, t, (t & 128) == 0, 512);      // k = 1024
    block_merge<256>(v, s, t, (cx & 1)  == 0, 1024);     // k = 2048

    float4* dst = (float4*)(g_A + b * NN + cx * 2048);
    dst[t * 2]     = make_float4(v[0], v[1], v[2], v[3]);
    dst[t * 2 + 1] = make_float4(v[4], v[5], v[6], v[7]);
}

// ---------------------------------------------------------------------------
// K2: cluster (2 CTAs x 512 thr) per batch. Each CTA owns 4096 elements.
//   k=4096 block-local; k=8192 j=4096 via DSMEM peer exchange; j<=2048 local.
//   Then K-window with 20-wide peer-smem halo -> g_pack.
// ---------------------------------------------------------------------------
#define EXTOFF 20
__global__ void __launch_bounds__(512, 1) __cluster_dims__(2, 1, 1)
k_cluster_merge_window() {
    __shared__ alignas(16) float s[EXTOFF + 4096 + EXTOFF];  // exchange & ext alias
    const int t = threadIdx.x;
    const int b = blockIdx.y;
    const unsigned r = blockIdx.x;          // rank in cluster
    const unsigned peer = r ^ 1u;
    float4* sA = (float4*)s;
    float4* sB = sA + 512;

    float v[EPT];
    { const float4* src = (const float4*)(g_A + b * NN + r * 4096);
      float4 a = src[t * 2], c = src[t * 2 + 1];
      v[0]=a.x; v[1]=a.y; v[2]=a.z; v[3]=a.w;
      v[4]=c.x; v[5]=c.y; v[6]=c.z; v[7]=c.w; }

    // k = 4096 (block-local): direction = (i & 4096)==0 -> rank 0 asc
    block_merge<512>(v, sA, t, r == 0, 2048);

    // k = 8192, j = 4096: cross-CTA compare-exchange (final stage -> ascending)
    sA[t] = make_float4(v[0], v[1], v[2], v[3]);
    sB[t] = make_float4(v[4], v[5], v[6], v[7]);
    CLUSTER_SYNC();
    {
        float4 pa = dsmem_read4(&sA[t], peer);
        float4 pb = dsmem_read4(&sB[t], peer);
        if (r == 0) {
            v[0]=fminf(v[0],pa.x); v[1]=fminf(v[1],pa.y); v[2]=fminf(v[2],pa.z); v[3]=fminf(v[3],pa.w);
            v[4]=fminf(v[4],pb.x); v[5]=fminf(v[5],pb.y); v[6]=fminf(v[6],pb.z); v[7]=fminf(v[7],pb.w);
        } else {
            v[0]=fmaxf(v[0],pa.x); v[1]=fmaxf(v[1],pa.y); v[2]=fmaxf(v[2],pa.z); v[3]=fmaxf(v[3],pa.w);
            v[4]=fmaxf(v[4],pb.x); v[5]=fmaxf(v[5],pb.y); v[6]=fmaxf(v[6],pb.z); v[7]=fmaxf(v[7],pb.w);
        }
    }
    CLUSTER_SYNC();   // peers done reading old exchange data before we overwrite

    // k = 8192, j = 2048..1 (block-local, ascending)
    block_merge<512>(v, sA, t, true, 2048);

    // natural layout at s[EXTOFF ..] (offset 80B keeps 16B alignment)
    { float4* nat = (float4*)(s + EXTOFF);
      nat[t * 2]     = make_float4(v[0], v[1], v[2], v[3]);
      nat[t * 2 + 1] = make_float4(v[4], v[5], v[6], v[7]); }
    CLUSTER_SYNC();   // natural arrays visible cluster-wide

    // halo: 20 edge values from peer
    if (t < EXTOFF) {
        if (r == 0)  // right halo: peer natural[0..19]
            s[EXTOFF + 4096 + t] = dsmem_read1(&s[EXTOFF + t], peer);
        else         // left halo: peer natural[4076..4095]
            s[t] = dsmem_read1(&s[4096 + t], peer);
    }
    CLUSTER_SYNC();   // halo reads done; no peer access after this -> exit-safe

    // K-window greedy expansion: 8 interleaved chains, global indices.
    const int baseg = r * 4096;
    int   lo[EPT], hi[EPT];
    float dl[EPT], dr[EPT];
    #pragma unroll
    for (int m = 0; m < EPT; m++) {
        int p = baseg + t * EPT + m;
        lo[m] = p; hi[m] = p;
        dl[m] = (p > 0)      ? (v[m] - s[p - 1 - baseg + EXTOFF]) : FLT_MAX;
        dr[m] = (p < NN - 1) ? (s[p + 1 - baseg + EXTOFF] - v[m]) : FLT_MAX;
    }
    for (int it = 1; it < KNN; it++) {
        #pragma unroll
        for (int m = 0; m < EPT; m++) {
            if (dl[m] <= dr[m]) {
                lo[m]--;
                dl[m] = (lo[m] > 0) ? (v[m] - s[lo[m] - 1 - baseg + EXTOFF]) : FLT_MAX;
            } else {
                hi[m]++;
                dr[m] = (hi[m] < NN - 1) ? (s[hi[m] + 1 - baseg + EXTOFF] - v[m]) : FLT_MAX;
            }
        }
    }

    float4* gp = g_pack + b * NN + baseg;
    #pragma unroll
    for (int m = 0; m < EPT; m++) {
        int p = t * EPT + m;
        gp[p] = make_float4(v[m],
                            s[lo[m] - baseg + EXTOFF] - v[m],
                            s[hi[m] - baseg + EXTOFF] - v[m], 0.f);
    }
}

// ---------------------------------------------------------------------------
// K3: reduce (max & mean per (batch,channel)) + fused FC via atomicAdd.
// ---------------------------------------------------------------------------
__global__ void __launch_bounds__(256) reduce_fc(const float* __restrict__ conv_w,
                                                 const float* __restrict__ gamma,
                                                 const float* __restrict__ beta,
                                                 const float* __restrict__ mean,
                                                 const float* __restrict__ var,
                                                 const float* __restrict__ lin_w,
                                                 float* __restrict__ out) {
    __shared__ float smx[8], ssm[8], bx1, bx2;
    const int b = blockIdx.x >> 6;
    const int o = blockIdx.x & 63;

    const float w0 = conv_w[o * 2 + 0];
    const float w1 = conv_w[o * 2 + 1];
    const float sc = gamma[o] * rsqrtf(var[o] + BN_EPS);
    const float sh = beta[o] - mean[o] * sc;
    const bool pos = (sc >= 0.f);

    const float4* __restrict__ gp = g_pack + b * NN;
    float mx = 0.f, sum = 0.f;
    #pragma unroll 4
    for (int p = threadIdx.x; p < NN; p += 256) {
        float4 q = gp[p];
        float e = pos ? fmaxf(w0 * q.y, w0 * q.z)
                      : fminf(w0 * q.y, w0 * q.z);
        float h = fmaxf(fmaf(sc, fmaf(w1, q.x, e), sh), 0.f);
        mx = fmaxf(mx, h);
        sum += h;
    }
    #pragma unroll
    for (int off = 16; off > 0; off >>= 1) {
        mx  = fmaxf(mx, __shfl_xor_sync(0xffffffffu, mx, off));
        sum += __shfl_xor_sync(0xffffffffu, sum, off);
    }
    const int warp = threadIdx.x >> 5, lane = threadIdx.x & 31;
    if (lane == 0) { smx[warp] = mx; ssm[warp] = sum; }
    __syncthreads();
    if (threadIdx.x == 0) {
        float fmx = smx[0], fsm = ssm[0];
        #pragma unroll
        for (int w = 1; w < 8; w++) { fmx = fmaxf(fmx, smx[w]); fsm += ssm[w]; }
        bx1 = fmx;
        bx2 = fsm * (1.0f / NN);
    }
    __syncthreads();
    if (threadIdx.x < NCLASS) {
        const int c = threadIdx.x;
        float contr = lin_w[c * (2 * COUT) + o]        * bx1
                    + lin_w[c * (2 * COUT) + COUT + o] * bx2;
        atomicAdd(&out[b * NCLASS + c], contr);
    }
}

// ---------------------------------------------------------------------------
extern "C" void kernel_launch(void* const* d_in, const int* in_sizes, int n_in,
                              void* d_out, int out_size) {
    const float* x      = (const float*)d_in[0];
    const float* conv_w = (const float*)d_in[1];
    const float* gamma  = (const float*)d_in[2];
    const float* beta   = (const float*)d_in[3];
    const float* mean   = (const float*)d_in[4];
    const float* var    = (const float*)d_in[5];
    const float* lin_w  = (const float*)d_in[6];
    float* out = (float*)d_out;

    k_sort2048<<<dim3(4, NB), 256>>>(x, out);           // k <= 2048 (+ zero out)
    k_cluster_merge_window<<<dim3(2, NB), 512>>>();     // k = 4096..8192 + window
    reduce_fc<<<NB * COUT, 256>>>(conv_w, gamma, beta, mean, var, lin_w, out);
}

// round 7
// speedup vs baseline: 1.7664x; 1.7664x over previous
#include <cuda_runtime.h>
#include <float.h>

#define NB     2
#define NN     8192
#define KNN    20
#define COUT   64
#define NCLASS 40
#define BN_EPS 1e-5f
#define EPT    8

// Scratch (no allocations allowed)
__device__ alignas(16) float  g_A[NB * NN];
__device__ alignas(16) float  g_B[NB * NN];
__device__ alignas(16) float4 g_pack[NB * NN];   // {x, dmin, dmax, 0}

// ---------------------------------------------------------------------------
// Compare-exchange helpers — ALL register indices compile-time constant.
// Global bitonic rule: at stage k, element i merges ascending iff (i&k)==0.
// ---------------------------------------------------------------------------
__device__ __forceinline__ void ce(float& a, float& b, bool up) {
    float mn = fminf(a, b), mx = fmaxf(a, b);
    a = up ? mn : mx;
    b = up ? mx : mn;
}

__device__ __forceinline__ void reg_merge(float v[EPT], bool d) {
    ce(v[0], v[4], d); ce(v[1], v[5], d); ce(v[2], v[6], d); ce(v[3], v[7], d);
    ce(v[0], v[2], d); ce(v[1], v[3], d); ce(v[4], v[6], d); ce(v[5], v[7], d);
    ce(v[0], v[1], d); ce(v[2], v[3], d); ce(v[4], v[5], d); ce(v[6], v[7], d);
}

__device__ __forceinline__ void sort8(float v[EPT], bool d8) {
    ce(v[0], v[1], true);  ce(v[2], v[3], false);
    ce(v[4], v[5], true);  ce(v[6], v[7], false);
    ce(v[0], v[2], true);  ce(v[1], v[3], true);
    ce(v[4], v[6], false); ce(v[5], v[7], false);
    ce(v[0], v[1], true);  ce(v[2], v[3], true);
    ce(v[4], v[5], false); ce(v[6], v[7], false);
    reg_merge(v, d8);
}

__device__ __forceinline__ void warp_merge(float v[EPT], bool d, int xm_start, int t) {
    for (int xm = xm_start; xm >= 1; xm >>= 1) {
        bool lowup = (((t & xm) == 0) == d);
        #pragma unroll
        for (int m = 0; m < EPT; m++) {
            float pv = __shfl_xor_sync(0xffffffffu, v[m], xm);
            v[m] = lowup ? fminf(v[m], pv) : fmaxf(v[m], pv);
        }
    }
    reg_merge(v, d);
}

// smem substages j = jstart..256, then intra-warp tail (j<=128).
template<int T>
__device__ __forceinline__ void block_merge(float v[EPT], float4* sA, int t,
                                            bool d, int jstart) {
    float4* sB = sA + T;
    for (int j = jstart; j >= 256; j >>= 1) {
        sA[t] = make_float4(v[0], v[1], v[2], v[3]);
        sB[t] = make_float4(v[4], v[5], v[6], v[7]);
        __syncthreads();
        const int  pt    = t ^ (j >> 3);
        const bool lowup = (((t & (j >> 3)) == 0) == d);
        float4 pa = sA[pt], pb = sB[pt];
        v[0] = lowup ? fminf(v[0], pa.x) : fmaxf(v[0], pa.x);
        v[1] = lowup ? fminf(v[1], pa.y) : fmaxf(v[1], pa.y);
        v[2] = lowup ? fminf(v[2], pa.z) : fmaxf(v[2], pa.z);
        v[3] = lowup ? fminf(v[3], pa.w) : fmaxf(v[3], pa.w);
        v[4] = lowup ? fminf(v[4], pb.x) : fmaxf(v[4], pb.x);
        v[5] = lowup ? fminf(v[5], pb.y) : fmaxf(v[5], pb.y);
        v[6] = lowup ? fminf(v[6], pb.z) : fmaxf(v[6], pb.z);
        v[7] = lowup ? fminf(v[7], pb.w) : fmaxf(v[7], pb.w);
        __syncthreads();
    }
    warp_merge(v, d, 16, t);
}

__device__ __forceinline__ float4 f4ce(float4 a, float4 b, bool mn) {
    float4 r;
    r.x = mn ? fminf(a.x, b.x) : fmaxf(a.x, b.x);
    r.y = mn ? fminf(a.y, b.y) : fmaxf(a.y, b.y);
    r.z = mn ? fminf(a.z, b.z) : fmaxf(a.z, b.z);
    r.w = mn ? fminf(a.w, b.w) : fmaxf(a.w, b.w);
    return r;
}

// ---------------------------------------------------------------------------
// K1: sort each 1024-chunk (k = 2..1024). grid (8, NB) x 128 threads.
// Also zeroes d_out (poisoned by harness) for the atomic FC accumulation.
// ---------------------------------------------------------------------------
__global__ void __launch_bounds__(128, 1) k_sort1024(const float* __restrict__ x,
                                                     float* __restrict__ out) {
    __shared__ float4 s[256];
    const int t = threadIdx.x;
    const int b = blockIdx.y, cx = blockIdx.x;
    if (b == 0 && cx == 0 && t < NB * NCLASS) out[t] = 0.f;

    const float4* src = (const float4*)(x + b * NN + cx * 1024);
    float v[EPT];
    { float4 a = src[t * 2], c = src[t * 2 + 1];
      v[0]=a.x; v[1]=a.y; v[2]=a.z; v[3]=a.w;
      v[4]=c.x; v[5]=c.y; v[6]=c.z; v[7]=c.w; }

    sort8(v, (t & 1) == 0);                            // k = 2,4,8
    for (int k = 16; k <= 256; k <<= 1)                // k = 16..256
        warp_merge(v, (t & (k >> 3)) == 0, k >> 4, t);
    block_merge<128>(v, s, t, (t & 64) == 0, 256);     // k = 512
    block_merge<128>(v, s, t, (cx & 1) == 0, 512);     // k = 1024

    float4* dst = (float4*)(g_A + b * NN + cx * 1024);
    dst[t * 2]     = make_float4(v[0], v[1], v[2], v[3]);
    dst[t * 2 + 1] = make_float4(v[4], v[5], v[6], v[7]);
}

// ---------------------------------------------------------------------------
// Merge stage for k = 1024<<L. Cross substages (j >= 1024) are collapsed into
// a per-element register butterfly at load time — ops are UNIFORM per block
// (they depend only on chunk-index bits). Then local j<=512 finishes.
// grid (8, NB) x 128 threads, each block owns one 1024-chunk.
// Src/dst are selected from the __device__ symbols IN DEVICE CODE
// (host code must not take the address of a __device__ variable).
//   L=1: g_A -> g_B     L=2: g_B -> g_A     L=3: g_A -> g_B
// ---------------------------------------------------------------------------
template<int L>
__global__ void __launch_bounds__(128, 1) k_merge() {
    __shared__ float4 s[256];
    const int t = threadIdx.x;
    const int b = blockIdx.y, cx = blockIdx.x;
    const float* __restrict__ srcp = (L == 2) ? g_B : g_A;
    float*       __restrict__ dstp = (L == 2) ? g_A : g_B;
    const float4* src = (const float4*)(srcp + b * NN);

    bool asc, km1, km2 = false, km3 = false;
    if (L == 1) {        // k = 2048: j=1024 cross
        asc = ((cx >> 1) & 1) == 0;
        km1 = asc == ((cx & 1) == 0);
    } else if (L == 2) { // k = 4096: j=2048,1024 cross
        asc = ((cx >> 2) & 1) == 0;
        km1 = asc == (((cx >> 1) & 1) == 0);
        km2 = asc == ((cx & 1) == 0);
    } else {             // k = 8192: j=4096,2048,1024 cross (final, ascending)
        asc = true;
        km1 = (cx & 4) == 0;
        km2 = (cx & 2) == 0;
        km3 = (cx & 1) == 0;
    }

    float v[EPT];
    #pragma unroll
    for (int g = 0; g < 2; g++) {
        const int o = t * 2 + g;
        float4 r;
        if (L == 1) {
            float4 a0 = src[cx * 256 + o], a1 = src[(cx ^ 1) * 256 + o];
            r = f4ce(a0, a1, km1);
        } else if (L == 2) {
            float4 a0 = src[cx * 256 + o],       a1 = src[(cx ^ 1) * 256 + o];
            float4 a2 = src[(cx ^ 2) * 256 + o], a3 = src[(cx ^ 3) * 256 + o];
            r = f4ce(f4ce(a0, a2, km1), f4ce(a1, a3, km1), km2);
        } else {
            float4 a0 = src[cx * 256 + o],       a1 = src[(cx ^ 1) * 256 + o];
            float4 a2 = src[(cx ^ 2) * 256 + o], a3 = src[(cx ^ 3) * 256 + o];
            float4 a4 = src[(cx ^ 4) * 256 + o], a5 = src[(cx ^ 5) * 256 + o];
            float4 a6 = src[(cx ^ 6) * 256 + o], a7 = src[(cx ^ 7) * 256 + o];
            float4 u0 = f4ce(a0, a4, km1), u2 = f4ce(a2, a6, km1);
            float4 u1 = f4ce(a1, a5, km1), u3 = f4ce(a3, a7, km1);
            r = f4ce(f4ce(u0, u2, km2), f4ce(u1, u3, km2), km3);
        }
        v[g * 4 + 0] = r.x; v[g * 4 + 1] = r.y;
        v[g * 4 + 2] = r.z; v[g * 4 + 3] = r.w;
    }

    block_merge<128>(v, s, t, asc, 512);   // j = 512..1 (block-local)

    float4* dst = (float4*)(dstp + b * NN + cx * 1024);
    dst[t * 2]     = make_float4(v[0], v[1], v[2], v[3]);
    dst[t * 2 + 1] = make_float4(v[4], v[5], v[6], v[7]);
}

// ---------------------------------------------------------------------------
// Window: K-nearest window per point on the sorted array (smem halo +-19).
// grid (32, NB) x 256 threads, one point per thread. Reads g_B (final sorted).
// ---------------------------------------------------------------------------
__global__ void __launch_bounds__(256) k_window() {
    __shared__ float sw[256 + 2 * (KNN - 1) + 2];
    const int b = blockIdx.y;
    const int p0 = blockIdx.x * 256;
    const float* __restrict__ src = g_B + b * NN;

    for (int i = threadIdx.x; i < 256 + 2 * (KNN - 1); i += 256) {
        int g = p0 - (KNN - 1) + i;
        sw[i] = (g >= 0 && g < NN) ? src[g] : 0.f;   // halo garbage never read
    }
    __syncthreads();

    const int p   = p0 + threadIdx.x;
    const int off = (KNN - 1) - p0;
    const float xv = sw[p + off];
    int lo = p, hi = p;
    float dl = (lo > 0)      ? (xv - sw[lo - 1 + off]) : FLT_MAX;
    float dr = (hi < NN - 1) ? (sw[hi + 1 + off] - xv) : FLT_MAX;
    #pragma unroll
    for (int it = 1; it < KNN; it++) {
        if (dl <= dr) {
            lo--;
            dl = (lo > 0) ? (xv - sw[lo - 1 + off]) : FLT_MAX;
        } else {
            hi++;
            dr = (hi < NN - 1) ? (sw[hi + 1 + off] - xv) : FLT_MAX;
        }
    }
    g_pack[b * NN + p] = make_float4(xv, sw[lo + off] - xv, sw[hi + off] - xv, 0.f);
}

// ---------------------------------------------------------------------------
// Reduce (max & mean per (batch,channel)) + fused FC via atomicAdd.
// ---------------------------------------------------------------------------
__global__ void __launch_bounds__(256) reduce_fc(const float* __restrict__ conv_w,
                                                 const float* __restrict__ gamma,
                                                 const float* __restrict__ beta,
                                                 const float* __restrict__ mean,
                                                 const float* __restrict__ var,
                                                 const float* __restrict__ lin_w,
                                                 float* __restrict__ out) {
    __shared__ float smx[8], ssm[8], bx1, bx2;
    const int b = blockIdx.x >> 6;
    const int o = blockIdx.x & 63;

    const float w0 = conv_w[o * 2 + 0];
    const float w1 = conv_w[o * 2 + 1];
    const float sc = gamma[o] * rsqrtf(var[o] + BN_EPS);
    const float sh = beta[o] - mean[o] * sc;
    const bool pos = (sc >= 0.f);

    const float4* __restrict__ gp = g_pack + b * NN;
    float mx = 0.f, sum = 0.f;
    #pragma unroll 4
    for (int p = threadIdx.x; p < NN; p += 256) {
        float4 q = gp[p];
        float e = pos ? fmaxf(w0 * q.y, w0 * q.z)
                      : fminf(w0 * q.y, w0 * q.z);
        float h = fmaxf(fmaf(sc, fmaf(w1, q.x, e), sh), 0.f);
        mx = fmaxf(mx, h);
        sum += h;
    }
    #pragma unroll
    for (int off = 16; off > 0; off >>= 1) {
        mx  = fmaxf(mx, __shfl_xor_sync(0xffffffffu, mx, off));
        sum += __shfl_xor_sync(0xffffffffu, sum, off);
    }
    const int warp = threadIdx.x >> 5, lane = threadIdx.x & 31;
    if (lane == 0) { smx[warp] = mx; ssm[warp] = sum; }
    __syncthreads();
    if (threadIdx.x == 0) {
        float fmx = smx[0], fsm = ssm[0];
        #pragma unroll
        for (int w = 1; w < 8; w++) { fmx = fmaxf(fmx, smx[w]); fsm += ssm[w]; }
        bx1 = fmx;
        bx2 = fsm * (1.0f / NN);
    }
    __syncthreads();
    if (threadIdx.x < NCLASS) {
        const int c = threadIdx.x;
        float contr = lin_w[c * (2 * COUT) + o]        * bx1
                    + lin_w[c * (2 * COUT) + COUT + o] * bx2;
        atomicAdd(&out[b * NCLASS + c], contr);
    }
}

// ---------------------------------------------------------------------------
extern "C" void kernel_launch(void* const* d_in, const int* in_sizes, int n_in,
                              void* d_out, int out_size) {
    const float* x      = (const float*)d_in[0];
    const float* conv_w = (const float*)d_in[1];
    const float* gamma  = (const float*)d_in[2];
    const float* beta   = (const float*)d_in[3];
    const float* mean   = (const float*)d_in[4];
    const float* var    = (const float*)d_in[5];
    const float* lin_w  = (const float*)d_in[6];
    float* out = (float*)d_out;

    k_sort1024<<<dim3(8, NB), 128>>>(x, out);   // k <= 1024   x   -> g_A
    k_merge<1><<<dim3(8, NB), 128>>>();         // k = 2048    g_A -> g_B
    k_merge<2><<<dim3(8, NB), 128>>>();         // k = 4096    g_B -> g_A
    k_merge<3><<<dim3(8, NB), 128>>>();         // k = 8192    g_A -> g_B
    k_window<<<dim3(32, NB), 256>>>();          // g_B -> g_pack
    reduce_fc<<<NB * COUT, 256>>>(conv_w, gamma, beta, mean, var, lin_w, out);
}